// round 2
// baseline (speedup 1.0000x reference)
#include <cuda_runtime.h>
#include <math.h>

// Problem constants
#define B_SZ   256
#define IN_SZ  512
#define OUT_SZ 512
#define R_SZ   4
#define H_SZ   4608            // (IN+OUT)*R + OUT
#define G4_SZ  (4*H_SZ)        // 18432
#define K_TOT  (IN_SZ + H_SZ)  // 5120

// GEMM tile config
#define BM 128
#define BN 128
#define BK 16
#define TM 8
#define TN 8
#define NTHREADS 256

// Scratch (no cudaMalloc allowed)
__device__ float g_gates[B_SZ * G4_SZ];   // 18.9 MB
__device__ float g_z[B_SZ * R_SZ];

// ---------------------------------------------------------------------------
// Kernel 1: gates = [x | h0] @ [W_ih | W_hh]^T + (b_ih + b_hh)
// A: logical [256 x 5120] (x for k<512, h0 for k>=512), row-major
// B: logical [18432 x 5120] (W_ih for k<512, W_hh for k>=512), row-major
// C: [256 x 18432] row-major into g_gates
// ---------------------------------------------------------------------------
__global__ __launch_bounds__(NTHREADS)
void gates_gemm(const float* __restrict__ x,  const float* __restrict__ h0,
                const float* __restrict__ Wih, const float* __restrict__ Whh,
                const float* __restrict__ bih, const float* __restrict__ bhh)
{
    __shared__ float As[2][BK][BM];
    __shared__ float Bs[2][BK][BN];

    const int tid = threadIdx.x;
    const int bm  = blockIdx.y * BM;
    const int bn  = blockIdx.x * BN;

    const int tr = (tid / 16) * TM;   // row offset within tile
    const int tc = (tid % 16) * TN;   // col offset within tile

    // Each thread loads 2 float4 for A and 2 float4 for B per k-step.
    // v in [0,512): row = v>>2 (128 rows), kchunk = (v&3)*4 (16 k per tile)
    const int vA0 = tid, vA1 = tid + 256;

    float acc[TM][TN];
#pragma unroll
    for (int i = 0; i < TM; i++)
#pragma unroll
        for (int j = 0; j < TN; j++) acc[i][j] = 0.f;

    auto ldA = [&](int k0, int v) -> float4 {
        int m = bm + (v >> 2);
        int k = k0 + ((v & 3) << 2);
        const float* p = (k < IN_SZ) ? (x + m * IN_SZ + k)
                                     : (h0 + m * H_SZ + (k - IN_SZ));
        return *reinterpret_cast<const float4*>(p);
    };
    auto ldB = [&](int k0, int v) -> float4 {
        int n = bn + (v >> 2);
        int k = k0 + ((v & 3) << 2);
        const float* p = (k < IN_SZ) ? (Wih + (long)n * IN_SZ + k)
                                     : (Whh + (long)n * H_SZ + (k - IN_SZ));
        return *reinterpret_cast<const float4*>(p);
    };
    auto stA = [&](int buf, int v, float4 val) {
        int m = v >> 2, k = (v & 3) << 2;
        As[buf][k + 0][m] = val.x; As[buf][k + 1][m] = val.y;
        As[buf][k + 2][m] = val.z; As[buf][k + 3][m] = val.w;
    };
    auto stB = [&](int buf, int v, float4 val) {
        int n = v >> 2, k = (v & 3) << 2;
        Bs[buf][k + 0][n] = val.x; Bs[buf][k + 1][n] = val.y;
        Bs[buf][k + 2][n] = val.z; Bs[buf][k + 3][n] = val.w;
    };

    // prologue: stage k0 = 0
    {
        float4 a0 = ldA(0, vA0), a1 = ldA(0, vA1);
        float4 b0 = ldB(0, vA0), b1 = ldB(0, vA1);
        stA(0, vA0, a0); stA(0, vA1, a1);
        stB(0, vA0, b0); stB(0, vA1, b1);
    }
    __syncthreads();

    int buf = 0;
    for (int k0 = BK; k0 < K_TOT; k0 += BK) {
        // issue next-tile global loads
        float4 a0 = ldA(k0, vA0), a1 = ldA(k0, vA1);
        float4 b0 = ldB(k0, vA0), b1 = ldB(k0, vA1);

        // compute on current buffer
#pragma unroll
        for (int k = 0; k < BK; k++) {
            float ar[TM], br[TN];
            *reinterpret_cast<float4*>(&ar[0]) = *reinterpret_cast<const float4*>(&As[buf][k][tr]);
            *reinterpret_cast<float4*>(&ar[4]) = *reinterpret_cast<const float4*>(&As[buf][k][tr + 4]);
            *reinterpret_cast<float4*>(&br[0]) = *reinterpret_cast<const float4*>(&Bs[buf][k][tc]);
            *reinterpret_cast<float4*>(&br[4]) = *reinterpret_cast<const float4*>(&Bs[buf][k][tc + 4]);
#pragma unroll
            for (int i = 0; i < TM; i++)
#pragma unroll
                for (int j = 0; j < TN; j++)
                    acc[i][j] = fmaf(ar[i], br[j], acc[i][j]);
        }

        // stage next buffer
        stA(buf ^ 1, vA0, a0); stA(buf ^ 1, vA1, a1);
        stB(buf ^ 1, vA0, b0); stB(buf ^ 1, vA1, b1);
        __syncthreads();
        buf ^= 1;
    }

    // last tile
#pragma unroll
    for (int k = 0; k < BK; k++) {
        float ar[TM], br[TN];
        *reinterpret_cast<float4*>(&ar[0]) = *reinterpret_cast<const float4*>(&As[buf][k][tr]);
        *reinterpret_cast<float4*>(&ar[4]) = *reinterpret_cast<const float4*>(&As[buf][k][tr + 4]);
        *reinterpret_cast<float4*>(&br[0]) = *reinterpret_cast<const float4*>(&Bs[buf][k][tc]);
        *reinterpret_cast<float4*>(&br[4]) = *reinterpret_cast<const float4*>(&Bs[buf][k][tc + 4]);
#pragma unroll
        for (int i = 0; i < TM; i++)
#pragma unroll
            for (int j = 0; j < TN; j++)
                acc[i][j] = fmaf(ar[i], br[j], acc[i][j]);
    }

    // epilogue: + bias, store
    float bb[TN];
#pragma unroll
    for (int j = 0; j < TN; j++) {
        int n = bn + tc + j;
        bb[j] = bih[n] + bhh[n];
    }
#pragma unroll
    for (int i = 0; i < TM; i++) {
        int m = bm + tr + i;
        float* out = g_gates + (long)m * G4_SZ + bn + tc;
        float4 v0, v1;
        v0.x = acc[i][0] + bb[0]; v0.y = acc[i][1] + bb[1];
        v0.z = acc[i][2] + bb[2]; v0.w = acc[i][3] + bb[3];
        v1.x = acc[i][4] + bb[4]; v1.y = acc[i][5] + bb[5];
        v1.z = acc[i][6] + bb[6]; v1.w = acc[i][7] + bb[7];
        *reinterpret_cast<float4*>(out)     = v0;
        *reinterpret_cast<float4*>(out + 4) = v1;
    }
}

// ---------------------------------------------------------------------------
// Kernel 2: LSTM elementwise -> h_new, c_new (written straight into d_out)
// ---------------------------------------------------------------------------
__device__ __forceinline__ float sigm(float v) { return 1.0f / (1.0f + expf(-v)); }

__global__ __launch_bounds__(256)
void lstm_eltwise(const float* __restrict__ c0,
                  float* __restrict__ h_out, float* __restrict__ c_out)
{
    int idx = blockIdx.x * blockDim.x + threadIdx.x;   // over B*H
    if (idx >= B_SZ * H_SZ) return;
    int b = idx / H_SZ;
    int h = idx - b * H_SZ;
    const float* gb = g_gates + (long)b * G4_SZ;
    float gi = sigm(gb[h]);
    float gf = sigm(gb[H_SZ + h]);
    float gg = tanhf(gb[2 * H_SZ + h]);
    float go = sigm(gb[3 * H_SZ + h]);
    float c  = gf * c0[idx] + gi * gg;
    float hn = go * tanhf(c);
    c_out[idx] = c;
    h_out[idx] = hn;
}

// ---------------------------------------------------------------------------
// Kernel 3: z[b,r] = dot(dw2[b,r,:], x[b,:]), dw2 = h_new[:, 2048 + r*512 + i]
// grid = B blocks, 128 threads (warp r handles one r)
// ---------------------------------------------------------------------------
__global__ __launch_bounds__(128)
void z_kernel(const float* __restrict__ hn, const float* __restrict__ x)
{
    int b    = blockIdx.x;
    int r    = threadIdx.x >> 5;
    int lane = threadIdx.x & 31;
    const float* dw2 = hn + (long)b * H_SZ + OUT_SZ * R_SZ + r * IN_SZ;
    const float* xb  = x + b * IN_SZ;
    float s = 0.f;
    for (int i = lane; i < IN_SZ; i += 32) s = fmaf(dw2[i], xb[i], s);
#pragma unroll
    for (int off = 16; off; off >>= 1) s += __shfl_xor_sync(0xffffffffu, s, off);
    if (lane == 0) g_z[b * R_SZ + r] = s;
}

// ---------------------------------------------------------------------------
// Kernel 4: y[b,o] = x[b]·W0[o] + sum_r dw1[b,o,r]*z[b,r] + db[b,o] + bias0[o]
// dw1[b,o,r] = h_new[b, o*4+r]; db[b,o] = h_new[b, 4096+o]
// Block handles 8 batches x all 512 outputs.
// ---------------------------------------------------------------------------
__global__ __launch_bounds__(512)
void y_kernel(const float* __restrict__ x, const float* __restrict__ hn,
              const float* __restrict__ W0, const float* __restrict__ bias0,
              float* __restrict__ y)
{
    __shared__ float xs[8][IN_SZ];
    __shared__ float zs[8][R_SZ];
    const int o     = threadIdx.x;
    const int bbase = blockIdx.x * 8;

    for (int t = threadIdx.x; t < 8 * IN_SZ; t += 512) {
        int bb = t >> 9, ii = t & 511;
        xs[bb][ii] = x[(bbase + bb) * IN_SZ + ii];
    }
    if (threadIdx.x < 32)
        zs[threadIdx.x >> 2][threadIdx.x & 3] = g_z[bbase * R_SZ + threadIdx.x];
    __syncthreads();

    float acc[8];
#pragma unroll
    for (int bb = 0; bb < 8; bb++) {
        const float* h = hn + (long)(bbase + bb) * H_SZ;
        float a = bias0[o] + h[OUT_SZ * R_SZ + IN_SZ * R_SZ + o];  // bias + db
#pragma unroll
        for (int r = 0; r < R_SZ; r++)
            a = fmaf(h[o * R_SZ + r], zs[bb][r], a);
        acc[bb] = a;
    }

    const float* w = W0 + (long)o * IN_SZ;
#pragma unroll 4
    for (int i = 0; i < IN_SZ; i++) {
        float wv = w[i];
#pragma unroll
        for (int bb = 0; bb < 8; bb++) acc[bb] = fmaf(wv, xs[bb][i], acc[bb]);
    }
#pragma unroll
    for (int bb = 0; bb < 8; bb++) y[(bbase + bb) * OUT_SZ + o] = acc[bb];
}

// ---------------------------------------------------------------------------
extern "C" void kernel_launch(void* const* d_in, const int* in_sizes, int n_in,
                              void* d_out, int out_size)
{
    const float* x     = (const float*)d_in[0];
    const float* h0    = (const float*)d_in[1];
    const float* c0    = (const float*)d_in[2];
    const float* Wih   = (const float*)d_in[3];
    const float* Whh   = (const float*)d_in[4];
    const float* bih   = (const float*)d_in[5];
    const float* bhh   = (const float*)d_in[6];
    const float* W0    = (const float*)d_in[7];
    const float* bias0 = (const float*)d_in[8];

    float* y     = (float*)d_out;                 // [B, OUT]
    float* h_out = y + B_SZ * OUT_SZ;             // [B, H]
    float* c_out = h_out + B_SZ * H_SZ;           // [B, H]

    dim3 ggrid(G4_SZ / BN, B_SZ / BM);            // (144, 2)
    gates_gemm<<<ggrid, NTHREADS>>>(x, h0, Wih, Whh, bih, bhh);

    int n = B_SZ * H_SZ;
    lstm_eltwise<<<(n + 255) / 256, 256>>>(c0, h_out, c_out);

    z_kernel<<<B_SZ, 128>>>(h_out, x);

    y_kernel<<<B_SZ / 8, 512>>>(x, h_out, W0, bias0, y);
}

// round 3
// speedup vs baseline: 2.1064x; 2.1064x over previous
#include <cuda_runtime.h>
#include <math.h>
#include <stdint.h>

// Problem constants
#define B_SZ   256
#define IN_SZ  512
#define OUT_SZ 512
#define R_SZ   4
#define H_SZ   4608            // (IN+OUT)*R + OUT
#define G4_SZ  (4*H_SZ)        // 18432  (gates columns)
#define NX_SZ  (G4_SZ + OUT_SZ) // 18944 (gates + x@W0^T columns) = 148*128
#define K_TOT  (IN_SZ + H_SZ)  // 5120

// GEMM tile config
#define BM 128
#define BN 128
#define BK 16
#define NTHREADS 256
#define SPAD 132               // padded leading dim for smem (conflict-free frags)

// Scratch (no cudaMalloc allowed)
__device__ float g_gates[B_SZ * NX_SZ];   // 19.4 MB
__device__ float g_z[B_SZ * R_SZ];

// ---------------------------------------------------------------------------
__device__ __forceinline__ float to_tf32(float x) {
    uint32_t u;
    asm("cvt.rna.tf32.f32 %0, %1;" : "=r"(u) : "f"(x));
    return __uint_as_float(u);
}

__device__ __forceinline__ void mma_tf32(float c[4],
                                         float a0, float a1, float a2, float a3,
                                         float b0, float b1) {
    asm volatile(
        "mma.sync.aligned.m16n8k8.row.col.f32.tf32.tf32.f32 "
        "{%0,%1,%2,%3}, {%4,%5,%6,%7}, {%8,%9}, {%0,%1,%2,%3};"
        : "+f"(c[0]), "+f"(c[1]), "+f"(c[2]), "+f"(c[3])
        : "r"(__float_as_uint(a0)), "r"(__float_as_uint(a1)),
          "r"(__float_as_uint(a2)), "r"(__float_as_uint(a3)),
          "r"(__float_as_uint(b0)), "r"(__float_as_uint(b1)));
}

// ---------------------------------------------------------------------------
// Kernel 1: C[m, n'] for n' < G4: [x|h0] @ [Wih|Whh]^T + (bih+bhh)
//           for n' >= G4:         x @ W0^T   (k >= IN contributes zero)
// A: [256 x 5120], B row n': weights row, C row-major stride NX_SZ.
// tf32 mma.sync, 128x128x16 tiles, 8 warps of 32x64.
// ---------------------------------------------------------------------------
__global__ __launch_bounds__(NTHREADS)
void gates_gemm(const float* __restrict__ x,  const float* __restrict__ h0,
                const float* __restrict__ Wih, const float* __restrict__ Whh,
                const float* __restrict__ bih, const float* __restrict__ bhh,
                const float* __restrict__ W0)
{
    __shared__ float As[2][BK][SPAD];
    __shared__ float Bs[2][BK][SPAD];

    const int tid = threadIdx.x;
    const int bm  = blockIdx.y * BM;
    const int bn  = blockIdx.x * BN;

    const int warp = tid >> 5;
    const int lane = tid & 31;
    const int wm0 = (warp & 3) * 32;   // warp m-strip (4 strips of 32)
    const int wn0 = (warp >> 2) * 64;  // warp n-strip (2 strips of 64)
    const int q  = lane & 3;           // k quad
    const int t8 = lane >> 2;          // row/col within 8

    const int vA0 = tid, vA1 = tid + 256;  // staging vector ids (v>>2 = row, (v&3)*4 = k)

    float acc[2][8][4];
#pragma unroll
    for (int mi = 0; mi < 2; mi++)
#pragma unroll
        for (int ni = 0; ni < 8; ni++)
#pragma unroll
            for (int e = 0; e < 4; e++) acc[mi][ni][e] = 0.f;

    auto ldA = [&](int k0, int v) -> float4 {
        int m = bm + (v >> 2);
        int k = k0 + ((v & 3) << 2);
        const float* p = (k < IN_SZ) ? (x + m * IN_SZ + k)
                                     : (h0 + m * H_SZ + (k - IN_SZ));
        return *reinterpret_cast<const float4*>(p);
    };
    auto ldB = [&](int k0, int v) -> float4 {
        int n = bn + (v >> 2);
        int k = k0 + ((v & 3) << 2);
        if (n < G4_SZ) {
            const float* p = (k < IN_SZ) ? (Wih + (long)n * IN_SZ + k)
                                         : (Whh + (long)n * H_SZ + (k - IN_SZ));
            return *reinterpret_cast<const float4*>(p);
        } else {
            if (k < IN_SZ) {
                const float* p = W0 + (long)(n - G4_SZ) * IN_SZ + k;
                return *reinterpret_cast<const float4*>(p);
            }
            return make_float4(0.f, 0.f, 0.f, 0.f);
        }
    };
    auto stA = [&](int buf, int v, float4 val) {
        int m = v >> 2, k = (v & 3) << 2;
        As[buf][k + 0][m] = to_tf32(val.x); As[buf][k + 1][m] = to_tf32(val.y);
        As[buf][k + 2][m] = to_tf32(val.z); As[buf][k + 3][m] = to_tf32(val.w);
    };
    auto stB = [&](int buf, int v, float4 val) {
        int n = v >> 2, k = (v & 3) << 2;
        Bs[buf][k + 0][n] = to_tf32(val.x); Bs[buf][k + 1][n] = to_tf32(val.y);
        Bs[buf][k + 2][n] = to_tf32(val.z); Bs[buf][k + 3][n] = to_tf32(val.w);
    };

    auto compute = [&](int buf) {
#pragma unroll
        for (int ks = 0; ks < 2; ks++) {
            const int kk = ks * 8;
            float a[2][4];
#pragma unroll
            for (int mi = 0; mi < 2; mi++) {
                int mr = wm0 + mi * 16 + t8;
                a[mi][0] = As[buf][kk + q][mr];
                a[mi][1] = As[buf][kk + q][mr + 8];
                a[mi][2] = As[buf][kk + q + 4][mr];
                a[mi][3] = As[buf][kk + q + 4][mr + 8];
            }
#pragma unroll
            for (int ni = 0; ni < 8; ni++) {
                int nc = wn0 + ni * 8 + t8;
                float b0 = Bs[buf][kk + q][nc];
                float b1 = Bs[buf][kk + q + 4][nc];
                mma_tf32(acc[0][ni], a[0][0], a[0][1], a[0][2], a[0][3], b0, b1);
                mma_tf32(acc[1][ni], a[1][0], a[1][1], a[1][2], a[1][3], b0, b1);
            }
        }
    };

    // prologue: stage k0 = 0
    {
        float4 a0 = ldA(0, vA0), a1 = ldA(0, vA1);
        float4 b0 = ldB(0, vA0), b1 = ldB(0, vA1);
        stA(0, vA0, a0); stA(0, vA1, a1);
        stB(0, vA0, b0); stB(0, vA1, b1);
    }
    __syncthreads();

    int buf = 0;
    for (int k0 = BK; k0 < K_TOT; k0 += BK) {
        float4 a0 = ldA(k0, vA0), a1 = ldA(k0, vA1);
        float4 b0 = ldB(k0, vA0), b1 = ldB(k0, vA1);

        compute(buf);

        stA(buf ^ 1, vA0, a0); stA(buf ^ 1, vA1, a1);
        stB(buf ^ 1, vA0, b0); stB(buf ^ 1, vA1, b1);
        __syncthreads();
        buf ^= 1;
    }
    compute(buf);

    // epilogue: + bias for gate columns, store
    const bool is_gate = (bn < G4_SZ);   // block-uniform (G4 is a multiple of 128)
#pragma unroll
    for (int ni = 0; ni < 8; ni++) {
        const int n2 = bn + wn0 + ni * 8 + q * 2;
        float bv0 = 0.f, bv1 = 0.f;
        if (is_gate) {
            bv0 = bih[n2] + bhh[n2];
            bv1 = bih[n2 + 1] + bhh[n2 + 1];
        }
#pragma unroll
        for (int mi = 0; mi < 2; mi++) {
            const int row = bm + wm0 + mi * 16 + t8;
            float2 v0 = make_float2(acc[mi][ni][0] + bv0, acc[mi][ni][1] + bv1);
            float2 v1 = make_float2(acc[mi][ni][2] + bv0, acc[mi][ni][3] + bv1);
            *reinterpret_cast<float2*>(g_gates + (long)row * NX_SZ + n2)        = v0;
            *reinterpret_cast<float2*>(g_gates + (long)(row + 8) * NX_SZ + n2)  = v1;
        }
    }
}

// ---------------------------------------------------------------------------
// Kernel 2: LSTM elementwise -> h_new, c_new
// ---------------------------------------------------------------------------
__device__ __forceinline__ float sigm(float v) { return 1.0f / (1.0f + expf(-v)); }

__global__ __launch_bounds__(256)
void lstm_eltwise(const float* __restrict__ c0,
                  float* __restrict__ h_out, float* __restrict__ c_out)
{
    int idx = blockIdx.x * blockDim.x + threadIdx.x;   // over B*H
    if (idx >= B_SZ * H_SZ) return;
    int b = idx / H_SZ;
    int h = idx - b * H_SZ;
    const float* gb = g_gates + (long)b * NX_SZ;
    float gi = sigm(gb[h]);
    float gf = sigm(gb[H_SZ + h]);
    float gg = tanhf(gb[2 * H_SZ + h]);
    float go = sigm(gb[3 * H_SZ + h]);
    float c  = gf * c0[idx] + gi * gg;
    float hn = go * tanhf(c);
    c_out[idx] = c;
    h_out[idx] = hn;
}

// ---------------------------------------------------------------------------
// Kernel 3: z[b,r] = dot(dw2[b,r,:], x[b,:])
// ---------------------------------------------------------------------------
__global__ __launch_bounds__(128)
void z_kernel(const float* __restrict__ hn, const float* __restrict__ x)
{
    int b    = blockIdx.x;
    int r    = threadIdx.x >> 5;
    int lane = threadIdx.x & 31;
    const float* dw2 = hn + (long)b * H_SZ + OUT_SZ * R_SZ + r * IN_SZ;
    const float* xb  = x + b * IN_SZ;
    float s = 0.f;
    for (int i = lane; i < IN_SZ; i += 32) s = fmaf(dw2[i], xb[i], s);
#pragma unroll
    for (int off = 16; off; off >>= 1) s += __shfl_xor_sync(0xffffffffu, s, off);
    if (lane == 0) g_z[b * R_SZ + r] = s;
}

// ---------------------------------------------------------------------------
// Kernel 4: y[b,o] = xw0[b,o] + bias0[o] + db[b,o] + sum_r dw1[b,o,r]*z[b,r]
// xw0 lives in g_gates columns [G4, G4+OUT); dw1 contiguous (float4).
// ---------------------------------------------------------------------------
__global__ __launch_bounds__(256)
void y_final(const float* __restrict__ hn, const float* __restrict__ bias0,
             float* __restrict__ y)
{
    int idx = blockIdx.x * blockDim.x + threadIdx.x;   // over B*OUT
    if (idx >= B_SZ * OUT_SZ) return;
    int b = idx >> 9;
    int o = idx & 511;
    const float* h = hn + (long)b * H_SZ;
    float v = g_gates[(long)b * NX_SZ + G4_SZ + o] + bias0[o]
            + h[OUT_SZ * R_SZ + IN_SZ * R_SZ + o];
    float4 w1 = *reinterpret_cast<const float4*>(h + o * R_SZ);
    const float* zb = g_z + b * R_SZ;
    v = fmaf(w1.x, zb[0], v);
    v = fmaf(w1.y, zb[1], v);
    v = fmaf(w1.z, zb[2], v);
    v = fmaf(w1.w, zb[3], v);
    y[idx] = v;
}

// ---------------------------------------------------------------------------
extern "C" void kernel_launch(void* const* d_in, const int* in_sizes, int n_in,
                              void* d_out, int out_size)
{
    const float* x     = (const float*)d_in[0];
    const float* h0    = (const float*)d_in[1];
    const float* c0    = (const float*)d_in[2];
    const float* Wih   = (const float*)d_in[3];
    const float* Whh   = (const float*)d_in[4];
    const float* bih   = (const float*)d_in[5];
    const float* bhh   = (const float*)d_in[6];
    const float* W0    = (const float*)d_in[7];
    const float* bias0 = (const float*)d_in[8];

    float* y     = (float*)d_out;                 // [B, OUT]
    float* h_out = y + B_SZ * OUT_SZ;             // [B, H]
    float* c_out = h_out + B_SZ * H_SZ;           // [B, H]

    dim3 ggrid(NX_SZ / BN, B_SZ / BM);            // (148, 2) = 296 blocks
    gates_gemm<<<ggrid, NTHREADS>>>(x, h0, Wih, Whh, bih, bhh, W0);

    int n = B_SZ * H_SZ;
    lstm_eltwise<<<(n + 255) / 256, 256>>>(c0, h_out, c_out);

    z_kernel<<<B_SZ, 128>>>(h_out, x);

    int m = B_SZ * OUT_SZ;
    y_final<<<(m + 255) / 256, 256>>>(h_out, bias0, y);
}

// round 5
// speedup vs baseline: 5.9764x; 2.8373x over previous
#include <cuda_runtime.h>
#include <cuda_fp16.h>
#include <math.h>
#include <stdint.h>

// Problem constants
#define B_SZ   256
#define IN_SZ  512
#define OUT_SZ 512
#define R_SZ   4
#define H_SZ   4608             // (IN+OUT)*R + OUT
#define G4_SZ  (4*H_SZ)         // 18432  (gate columns)
#define NX_SZ  (G4_SZ + OUT_SZ) // 18944  (gates + x@W0^T columns) = 148*128
#define K_TOT  (IN_SZ + H_SZ)   // 5120

// GEMM tile config (fp16 mma.sync m16n8k16)
#define BM 128
#define BN 128
#define BK 32                   // 32 halves of k per stage
#define BKP 40                  // padded row length (80 bytes = 20 banks, conflict-free)
#define NTHREADS 256

// Scratch (no cudaMalloc allowed)
__device__ float g_gates[B_SZ * NX_SZ];   // 19.4 MB
__device__ float g_z[B_SZ * R_SZ];

// ---------------------------------------------------------------------------
__device__ __forceinline__ void mma_f16(float c[4],
                                        uint32_t a0, uint32_t a1, uint32_t a2, uint32_t a3,
                                        uint32_t b0, uint32_t b1) {
    asm volatile(
        "mma.sync.aligned.m16n8k16.row.col.f32.f16.f16.f32 "
        "{%0,%1,%2,%3}, {%4,%5,%6,%7}, {%8,%9}, {%0,%1,%2,%3};"
        : "+f"(c[0]), "+f"(c[1]), "+f"(c[2]), "+f"(c[3])
        : "r"(a0), "r"(a1), "r"(a2), "r"(a3), "r"(b0), "r"(b1));
}

__device__ __forceinline__ uint32_t h2u(__half2 h) {
    return *reinterpret_cast<uint32_t*>(&h);
}

// ---------------------------------------------------------------------------
// Kernel 1: C[m, n'] row-major [256 x 18944] into g_gates:
//   n' < G4:  [x|h0] @ [Wih|Whh]^T + (bih+bhh)
//   n' >= G4: x @ W0^T   (K loop runs only over k<512 for these blocks)
// fp16 mma.sync, 128x128x32 stages, 8 warps of 32x64, double-buffered smem.
// ---------------------------------------------------------------------------
__global__ __launch_bounds__(NTHREADS, 2)
void gates_gemm(const float* __restrict__ x,  const float* __restrict__ h0,
                const float* __restrict__ Wih, const float* __restrict__ Whh,
                const float* __restrict__ bih, const float* __restrict__ bhh,
                const float* __restrict__ W0)
{
    __shared__ __align__(16) __half As[2][BM][BKP];
    __shared__ __align__(16) __half Bs[2][BN][BKP];

    const int tid = threadIdx.x;
    const int bm  = blockIdx.y * BM;
    const int bn  = blockIdx.x * BN;
    const bool isW0 = (bn >= G4_SZ);                 // block-uniform
    const int NIT = isW0 ? (IN_SZ / BK) : (K_TOT / BK);   // 16 or 160

    const int warp = tid >> 5;
    const int lane = tid & 31;
    const int wm0 = (warp & 3) * 32;   // warp m-strip
    const int wn0 = (warp >> 2) * 64;  // warp n-strip
    const int q   = lane & 3;          // k quad
    const int t8  = lane >> 2;         // row/col within 8

    float acc[2][8][4];
#pragma unroll
    for (int mi = 0; mi < 2; mi++)
#pragma unroll
        for (int ni = 0; ni < 8; ni++)
#pragma unroll
            for (int e = 0; e < 4; e++) acc[mi][ni][e] = 0.f;

    // staging registers: A tile 128x32 fl = 1024 float4 (4/thread), B same
    float4 ra[4], rb[4];

    auto ldg_tile = [&](int t) {
        const int k0 = t * BK;
        const float* baseA; long sA;
        if (k0 < IN_SZ) { baseA = x + (long)bm * IN_SZ + k0; sA = IN_SZ; }
        else            { baseA = h0 + (long)bm * H_SZ + (k0 - IN_SZ); sA = H_SZ; }
#pragma unroll
        for (int j = 0; j < 4; j++) {
            int ch = j * 256 + tid, row = ch >> 3, c = ch & 7;
            ra[j] = *reinterpret_cast<const float4*>(baseA + (long)row * sA + c * 4);
        }
        const float* baseB; long sB;
        if (isW0)           { baseB = W0 + (long)(bn - G4_SZ) * IN_SZ + k0; sB = IN_SZ; }
        else if (k0 < IN_SZ){ baseB = Wih + (long)bn * IN_SZ + k0; sB = IN_SZ; }
        else                { baseB = Whh + (long)bn * H_SZ + (k0 - IN_SZ); sB = H_SZ; }
#pragma unroll
        for (int j = 0; j < 4; j++) {
            int ch = j * 256 + tid, row = ch >> 3, c = ch & 7;
            rb[j] = *reinterpret_cast<const float4*>(baseB + (long)row * sB + c * 4);
        }
    };

    auto sts_tile = [&](int buf) {
#pragma unroll
        for (int j = 0; j < 4; j++) {
            int ch = j * 256 + tid, row = ch >> 3, c = ch & 7;
            __half2 h0a = __floats2half2_rn(ra[j].x, ra[j].y);
            __half2 h1a = __floats2half2_rn(ra[j].z, ra[j].w);
            *reinterpret_cast<uint2*>(&As[buf][row][c * 4]) = make_uint2(h2u(h0a), h2u(h1a));
        }
#pragma unroll
        for (int j = 0; j < 4; j++) {
            int ch = j * 256 + tid, row = ch >> 3, c = ch & 7;
            __half2 h0b = __floats2half2_rn(rb[j].x, rb[j].y);
            __half2 h1b = __floats2half2_rn(rb[j].z, rb[j].w);
            *reinterpret_cast<uint2*>(&Bs[buf][row][c * 4]) = make_uint2(h2u(h0b), h2u(h1b));
        }
    };

    auto compute = [&](int buf) {
#pragma unroll
        for (int ks = 0; ks < 2; ks++) {
            const int kb = ks * 16;
            uint32_t a[2][4];
#pragma unroll
            for (int mi = 0; mi < 2; mi++) {
                int r0 = wm0 + mi * 16 + t8;
                a[mi][0] = h2u(*reinterpret_cast<const __half2*>(&As[buf][r0    ][kb + 2 * q    ]));
                a[mi][1] = h2u(*reinterpret_cast<const __half2*>(&As[buf][r0 + 8][kb + 2 * q    ]));
                a[mi][2] = h2u(*reinterpret_cast<const __half2*>(&As[buf][r0    ][kb + 2 * q + 8]));
                a[mi][3] = h2u(*reinterpret_cast<const __half2*>(&As[buf][r0 + 8][kb + 2 * q + 8]));
            }
#pragma unroll
            for (int ni = 0; ni < 8; ni++) {
                int nc = wn0 + ni * 8 + t8;
                uint32_t b0 = h2u(*reinterpret_cast<const __half2*>(&Bs[buf][nc][kb + 2 * q    ]));
                uint32_t b1 = h2u(*reinterpret_cast<const __half2*>(&Bs[buf][nc][kb + 2 * q + 8]));
                mma_f16(acc[0][ni], a[0][0], a[0][1], a[0][2], a[0][3], b0, b1);
                mma_f16(acc[1][ni], a[1][0], a[1][1], a[1][2], a[1][3], b0, b1);
            }
        }
    };

    // prologue
    ldg_tile(0);
    sts_tile(0);
    __syncthreads();

    int buf = 0;
    for (int t = 1; t < NIT; t++) {
        ldg_tile(t);          // global loads for next stage
        compute(buf);         // mma on current stage
        sts_tile(buf ^ 1);    // convert + store next stage
        __syncthreads();
        buf ^= 1;
    }
    compute(buf);

    // epilogue: + bias for gate columns, store fp32
#pragma unroll
    for (int ni = 0; ni < 8; ni++) {
        const int n2 = bn + wn0 + ni * 8 + q * 2;
        float bv0 = 0.f, bv1 = 0.f;
        if (!isW0) {
            bv0 = bih[n2] + bhh[n2];
            bv1 = bih[n2 + 1] + bhh[n2 + 1];
        }
#pragma unroll
        for (int mi = 0; mi < 2; mi++) {
            const int row = bm + wm0 + mi * 16 + t8;
            float2 v0 = make_float2(acc[mi][ni][0] + bv0, acc[mi][ni][1] + bv1);
            float2 v1 = make_float2(acc[mi][ni][2] + bv0, acc[mi][ni][3] + bv1);
            *reinterpret_cast<float2*>(g_gates + (long)row * NX_SZ + n2)       = v0;
            *reinterpret_cast<float2*>(g_gates + (long)(row + 8) * NX_SZ + n2) = v1;
        }
    }
}

// ---------------------------------------------------------------------------
// Kernel 2: LSTM elementwise -> h_new, c_new
// ---------------------------------------------------------------------------
__device__ __forceinline__ float sigm(float v) { return 1.0f / (1.0f + expf(-v)); }

__global__ __launch_bounds__(256)
void lstm_eltwise(const float* __restrict__ c0,
                  float* __restrict__ h_out, float* __restrict__ c_out)
{
    int idx = blockIdx.x * blockDim.x + threadIdx.x;   // over B*H
    if (idx >= B_SZ * H_SZ) return;
    int b = idx / H_SZ;
    int h = idx - b * H_SZ;
    const float* gb = g_gates + (long)b * NX_SZ;
    float gi = sigm(gb[h]);
    float gf = sigm(gb[H_SZ + h]);
    float gg = tanhf(gb[2 * H_SZ + h]);
    float go = sigm(gb[3 * H_SZ + h]);
    float c  = gf * c0[idx] + gi * gg;
    float hn = go * tanhf(c);
    c_out[idx] = c;
    h_out[idx] = hn;
}

// ---------------------------------------------------------------------------
// Kernel 3: z[b,r] = dot(dw2[b,r,:], x[b,:])
// ---------------------------------------------------------------------------
__global__ __launch_bounds__(128)
void z_kernel(const float* __restrict__ hn, const float* __restrict__ x)
{
    int b    = blockIdx.x;
    int r    = threadIdx.x >> 5;
    int lane = threadIdx.x & 31;
    const float* dw2 = hn + (long)b * H_SZ + OUT_SZ * R_SZ + r * IN_SZ;
    const float* xb  = x + b * IN_SZ;
    float s = 0.f;
    for (int i = lane; i < IN_SZ; i += 32) s = fmaf(dw2[i], xb[i], s);
#pragma unroll
    for (int off = 16; off; off >>= 1) s += __shfl_xor_sync(0xffffffffu, s, off);
    if (lane == 0) g_z[b * R_SZ + r] = s;
}

// ---------------------------------------------------------------------------
// Kernel 4: y[b,o] = xw0[b,o] + bias0[o] + db[b,o] + sum_r dw1[b,o,r]*z[b,r]
// ---------------------------------------------------------------------------
__global__ __launch_bounds__(256)
void y_final(const float* __restrict__ hn, const float* __restrict__ bias0,
             float* __restrict__ y)
{
    int idx = blockIdx.x * blockDim.x + threadIdx.x;   // over B*OUT
    if (idx >= B_SZ * OUT_SZ) return;
    int b = idx >> 9;
    int o = idx & 511;
    const float* h = hn + (long)b * H_SZ;
    float v = g_gates[(long)b * NX_SZ + G4_SZ + o] + bias0[o]
            + h[OUT_SZ * R_SZ + IN_SZ * R_SZ + o];
    float4 w1 = *reinterpret_cast<const float4*>(h + o * R_SZ);
    const float* zb = g_z + b * R_SZ;
    v = fmaf(w1.x, zb[0], v);
    v = fmaf(w1.y, zb[1], v);
    v = fmaf(w1.z, zb[2], v);
    v = fmaf(w1.w, zb[3], v);
    y[idx] = v;
}

// ---------------------------------------------------------------------------
extern "C" void kernel_launch(void* const* d_in, const int* in_sizes, int n_in,
                              void* d_out, int out_size)
{
    const float* x     = (const float*)d_in[0];
    const float* h0    = (const float*)d_in[1];
    const float* c0    = (const float*)d_in[2];
    const float* Wih   = (const float*)d_in[3];
    const float* Whh   = (const float*)d_in[4];
    const float* bih   = (const float*)d_in[5];
    const float* bhh   = (const float*)d_in[6];
    const float* W0    = (const float*)d_in[7];
    const float* bias0 = (const float*)d_in[8];

    float* y     = (float*)d_out;                 // [B, OUT]
    float* h_out = y + B_SZ * OUT_SZ;             // [B, H]
    float* c_out = h_out + B_SZ * H_SZ;           // [B, H]

    dim3 ggrid(NX_SZ / BN, B_SZ / BM);            // (148, 2) = 296 blocks
    gates_gemm<<<ggrid, NTHREADS>>>(x, h0, Wih, Whh, bih, bhh, W0);

    int n = B_SZ * H_SZ;
    lstm_eltwise<<<(n + 255) / 256, 256>>>(c0, h_out, c_out);

    z_kernel<<<B_SZ, 128>>>(h_out, x);

    int m = B_SZ * OUT_SZ;
    y_final<<<(m + 255) / 256, 256>>>(h_out, bias0, y);
}